// round 14
// baseline (speedup 1.0000x reference)
#include <cuda_runtime.h>
#include <cuda_fp16.h>

#define N       4096
#define THREADS 256

__global__ __launch_bounds__(THREADS)
void fwht_kernel(const float* __restrict__ x,
                 const float* __restrict__ s,
                 float* __restrict__ out)
{
    __shared__ __half2 smA[2048];   // T1: per-warp 256-word regions, XOR-swizzled
    __shared__ __half2 smB[2048];   // T2: CTA-level, XOR-swizzled

    const int row  = blockIdx.x;
    const int t    = threadIdx.x;
    const int lane = t & 31;        // initially = (i2,i3,i4,i5,i6)
    const int w    = t >> 5;        // = (i9,i10,i11) throughout

    // ---- coalesced load: chunk = (w<<7)|(j<<5)|lane; each LDG.128 lane-contiguous ----
    // regs hold bits (i0,i1) [within float4] x (i7,i8) [=j]
    // x streams (evict-first); s is 16KB, L1/L2-resident after first wave (default caching)
    float v[16];
    const float4* xr4 = reinterpret_cast<const float4*>(x + (size_t)row * N);
    const float4* sr4 = reinterpret_cast<const float4*>(s);
    const int cbase = (w << 7) | lane;
    #pragma unroll
    for (int j = 0; j < 4; j++) {
        float4 f = __ldcs(xr4 + cbase + (j << 5));
        float4 g = __ldg (sr4 + cbase + (j << 5));
        v[4*j+0] = f.x * g.x;
        v[4*j+1] = f.y * g.y;
        v[4*j+2] = f.z * g.z;
        v[4*j+3] = f.w * g.w;
    }

    // ---- stage 1 (fp32): butterfly reg bits (i0,i1,i7,i8) = v-index bits 0..3 ----
    #pragma unroll
    for (int m = 1; m < 16; m <<= 1) {
        #pragma unroll
        for (int r = 0; r < 16; r++) {
            if ((r & m) == 0) {
                float a = v[r], b = v[r | m];
                v[r]     = a + b;
                v[r | m] = a - b;
            }
        }
    }

    // ---- pack along i0: h[u], u bits = (i1,i7,i8) ----
    __half2 h[8];
    #pragma unroll
    for (int u = 0; u < 8; u++)
        h[u] = __floats2half2_rn(v[2*u], v[2*u+1]);

    // ---- stage 2a: 2 full-exchange packed shuffle levels over lane bits i2, i3 ----
    const __half2 POS = __floats2half2_rn( 1.0f,  1.0f);
    const __half2 NEG = __floats2half2_rn(-1.0f, -1.0f);
    #pragma unroll
    for (int mm = 1; mm < 4; mm <<= 1) {
        const __half2 sgn2 = (lane & mm) ? NEG : POS;
        #pragma unroll
        for (int u = 0; u < 8; u++) {
            unsigned su = *reinterpret_cast<unsigned*>(&h[u]);
            unsigned ru = __shfl_xor_sync(0xffffffffu, su, mm);
            __half2 recv = *reinterpret_cast<__half2*>(&ru);
            h[u] = __hfma2(sgn2, h[u], recv);
        }
    }

    // ---- T1 (warp-local, XOR swizzle): words (i1,i7,i8) -> (i4,i5,i6) ----
    // addr8 = (i4|i5<<1|i6<<2)<<5 | [ (i8^i6) | i2<<1 | i3<<2 | (i1^i4)<<3 | (i7^i5)<<4 ]
    // write-varying lanes {i2,i3,i4,i5,i6} banks {2,4,8,16,1}; read-varying {i1,i2,i3,i7,i8} banks {8,2,4,16,1}
    {
        const int hi3w   = (w << 8) | ((lane >> 2) << 5);
        const int wbase5 = ((lane >> 4) & 1) | ((lane & 3) << 1) | (((lane >> 2) & 3) << 3);
        #pragma unroll
        for (int u = 0; u < 8; u++) {
            int uswz = ((u >> 2) & 1) | ((u & 1) << 3) | (((u >> 1) & 1) << 4);
            smA[hi3w | (wbase5 ^ uswz)] = h[u];
        }
    }
    __syncwarp();
    {
        // reader lane roles: L0=i1, L1=i2, L2=i3, L3=i7, L4=i8
        const int rbase5 = ((lane >> 4) & 1) | (((lane >> 1) & 1) << 1) | (((lane >> 2) & 1) << 2)
                         | ((lane & 1) << 3) | (((lane >> 3) & 1) << 4);
        #pragma unroll
        for (int k = 0; k < 8; k++) {
            int kswz = ((k >> 2) & 1) | ((k & 1) << 3) | (((k >> 1) & 1) << 4);
            h[k] = smA[(w << 8) | (k << 5) | (rbase5 ^ kswz)];
        }
    }

    // ---- stage 2b: packed butterfly over word bits (i4,i5,i6), 3 levels ----
    #pragma unroll
    for (int m = 1; m < 8; m <<= 1) {
        #pragma unroll
        for (int g = 0; g < 8; g++) {
            if ((g & m) == 0) {
                __half2 a = h[g], b = h[g | m];
                h[g]     = __hadd2(a, b);
                h[g | m] = __hsub2(a, b);
            }
        }
    }

    // ---- T2 (CTA-level, XOR swizzle): words (i4,i5,i6) -> (i9,i10,i11) ----
    // pos = (i4|i5<<1|i6<<2|i9<<3|i10<<4|i11<<5)<<5 | [ i1 | i2<<1 | i3<<2 | (i7^i4)<<3 | (i8^i5)<<4 ]
    {
        const int lw3 = lane & 7;   // i1,i2,i3
        #pragma unroll
        for (int g = 0; g < 8; g++) {
            int lo5 = lw3 | ((((lane >> 3) & 1) ^ (g & 1)) << 3)
                          | ((((lane >> 4) & 1) ^ ((g >> 1) & 1)) << 4);
            smB[((g | (w << 3)) << 5) | lo5] = h[g];
        }
    }
    __syncthreads();

    // reader lane roles: L0=i1..L4=i5; reader w = (i6,i7,i8); loop k2 = (i9,i10,i11)
    float uu[16];
    {
        const int lo5r = (lane & 7)
                       | (((((w >> 1) & 1) ^ ((lane >> 3) & 1))) << 3)
                       | (((((w >> 2) & 1) ^ ((lane >> 4) & 1))) << 4);
        const int hibase = ((lane >> 3) & 1) | (((lane >> 4) & 1) << 1) | ((w & 1) << 2);
        #pragma unroll
        for (int k2 = 0; k2 < 8; k2++) {
            float2 f = __half22float2(smB[((hibase | (k2 << 3)) << 5) | lo5r]);
            uu[2*k2]   = f.x;   // i0 = 0
            uu[2*k2+1] = f.y;   // i0 = 1
        }
    }

    // ---- stage 3 (fp32): butterfly k2 bits (i9,i10,i11) = uu-index bits 1..3 ----
    #pragma unroll
    for (int m = 2; m < 16; m <<= 1) {
        #pragma unroll
        for (int r = 0; r < 16; r++) {
            if ((r & m) == 0) {
                float a = uu[r], b = uu[r | m];
                uu[r]     = a + b;
                uu[r | m] = a - b;
            }
        }
    }

    // ---- scaled streaming store: o = (k2<<9)|(w<<6)|(lane<<1)|i0 -> 256B/warp contiguous ----
    const float scale = 0.015625f;   // 1/sqrt(4096)
    float* orow = out + (size_t)row * N;
    const int ob = (w << 6) | (lane << 1);
    #pragma unroll
    for (int k2 = 0; k2 < 8; k2++) {
        float2 f2 = make_float2(uu[2*k2] * scale, uu[2*k2+1] * scale);
        __stcs(reinterpret_cast<float2*>(orow + (ob | (k2 << 9))), f2);
    }
}

extern "C" void kernel_launch(void* const* d_in, const int* in_sizes, int n_in,
                              void* d_out, int out_size)
{
    const float* x = (const float*)d_in[0];
    const float* s = (const float*)d_in[1];
    float* out     = (float*)d_out;

    const int rows = in_sizes[0] / N;   // 16384
    fwht_kernel<<<rows, THREADS>>>(x, s, out);
}

// round 16
// speedup vs baseline: 1.0058x; 1.0058x over previous
#include <cuda_runtime.h>
#include <cuda_fp16.h>

#define N       4096
#define THREADS 256

__global__ __launch_bounds__(THREADS, 8)
void fwht_kernel(const float* __restrict__ x,
                 const float* __restrict__ s,
                 float* __restrict__ out)
{
    __shared__ __half2 smA[2048];   // T1: per-warp 256-word regions, XOR-swizzled
    __shared__ __half2 smB[2048];   // T2: CTA-level, XOR-swizzled

    const int row  = blockIdx.x;
    const int t    = threadIdx.x;
    const int lane = t & 31;        // initially = (i2,i3,i4,i5,i6)
    const int w    = t >> 5;        // = (i9,i10,i11) throughout

    // ---- coalesced load: chunk = (w<<7)|(j<<5)|lane; each LDG.128 lane-contiguous ----
    // regs hold bits (i0,i1) [within float4] x (i7,i8) [=j]
    // s (16KB, L1/L2-hot) issued first; x streams evict-first.
    // sign applied as integer XOR of the sign bit (exact: s = +-1.0f).
    float v[16];
    const uint4*  xr4 = reinterpret_cast<const uint4*>(x + (size_t)row * N);
    const uint4*  sr4 = reinterpret_cast<const uint4*>(s);
    const int cbase = (w << 7) | lane;

    uint4 sg[4];
    #pragma unroll
    for (int j = 0; j < 4; j++)
        sg[j] = __ldg(sr4 + cbase + (j << 5));

    #pragma unroll
    for (int j = 0; j < 4; j++) {
        uint4 f = __ldcs(xr4 + cbase + (j << 5));
        v[4*j+0] = __int_as_float((int)(f.x ^ (sg[j].x & 0x80000000u)));
        v[4*j+1] = __int_as_float((int)(f.y ^ (sg[j].y & 0x80000000u)));
        v[4*j+2] = __int_as_float((int)(f.z ^ (sg[j].z & 0x80000000u)));
        v[4*j+3] = __int_as_float((int)(f.w ^ (sg[j].w & 0x80000000u)));
    }

    // ---- stage 1 (fp32): butterfly reg bits (i0,i1,i7,i8) = v-index bits 0..3 ----
    #pragma unroll
    for (int m = 1; m < 16; m <<= 1) {
        #pragma unroll
        for (int r = 0; r < 16; r++) {
            if ((r & m) == 0) {
                float a = v[r], b = v[r | m];
                v[r]     = a + b;
                v[r | m] = a - b;
            }
        }
    }

    // ---- pack along i0: h[u], u bits = (i1,i7,i8) ----
    __half2 h[8];
    #pragma unroll
    for (int u = 0; u < 8; u++)
        h[u] = __floats2half2_rn(v[2*u], v[2*u+1]);

    // ---- stage 2a: 2 full-exchange packed shuffle levels over lane bits i2, i3 ----
    const __half2 POS = __floats2half2_rn( 1.0f,  1.0f);
    const __half2 NEG = __floats2half2_rn(-1.0f, -1.0f);
    #pragma unroll
    for (int mm = 1; mm < 4; mm <<= 1) {
        const __half2 sgn2 = (lane & mm) ? NEG : POS;
        #pragma unroll
        for (int u = 0; u < 8; u++) {
            unsigned su = *reinterpret_cast<unsigned*>(&h[u]);
            unsigned ru = __shfl_xor_sync(0xffffffffu, su, mm);
            __half2 recv = *reinterpret_cast<__half2*>(&ru);
            h[u] = __hfma2(sgn2, h[u], recv);
        }
    }

    // ---- T1 (warp-local, XOR swizzle): words (i1,i7,i8) -> (i4,i5,i6) ----
    // addr8 = (i4|i5<<1|i6<<2)<<5 | [ (i8^i6) | i2<<1 | i3<<2 | (i1^i4)<<3 | (i7^i5)<<4 ]
    {
        const int hi3w   = (w << 8) | ((lane >> 2) << 5);
        const int wbase5 = ((lane >> 4) & 1) | ((lane & 3) << 1) | (((lane >> 2) & 3) << 3);
        #pragma unroll
        for (int u = 0; u < 8; u++) {
            int uswz = ((u >> 2) & 1) | ((u & 1) << 3) | (((u >> 1) & 1) << 4);
            smA[hi3w | (wbase5 ^ uswz)] = h[u];
        }
    }
    __syncwarp();
    {
        // reader lane roles: L0=i1, L1=i2, L2=i3, L3=i7, L4=i8
        const int rbase5 = ((lane >> 4) & 1) | (((lane >> 1) & 1) << 1) | (((lane >> 2) & 1) << 2)
                         | ((lane & 1) << 3) | (((lane >> 3) & 1) << 4);
        #pragma unroll
        for (int k = 0; k < 8; k++) {
            int kswz = ((k >> 2) & 1) | ((k & 1) << 3) | (((k >> 1) & 1) << 4);
            h[k] = smA[(w << 8) | (k << 5) | (rbase5 ^ kswz)];
        }
    }

    // ---- stage 2b: packed butterfly over word bits (i4,i5,i6), 3 levels ----
    #pragma unroll
    for (int m = 1; m < 8; m <<= 1) {
        #pragma unroll
        for (int g = 0; g < 8; g++) {
            if ((g & m) == 0) {
                __half2 a = h[g], b = h[g | m];
                h[g]     = __hadd2(a, b);
                h[g | m] = __hsub2(a, b);
            }
        }
    }

    // ---- T2 (CTA-level, XOR swizzle): words (i4,i5,i6) -> (i9,i10,i11) ----
    // pos = (i4|i5<<1|i6<<2|i9<<3|i10<<4|i11<<5)<<5 | [ i1 | i2<<1 | i3<<2 | (i7^i4)<<3 | (i8^i5)<<4 ]
    {
        const int lw3 = lane & 7;   // i1,i2,i3
        #pragma unroll
        for (int g = 0; g < 8; g++) {
            int lo5 = lw3 | ((((lane >> 3) & 1) ^ (g & 1)) << 3)
                          | ((((lane >> 4) & 1) ^ ((g >> 1) & 1)) << 4);
            smB[((g | (w << 3)) << 5) | lo5] = h[g];
        }
    }
    __syncthreads();

    // reader lane roles: L0=i1..L4=i5; reader w = (i6,i7,i8); loop k2 = (i9,i10,i11)
    float uu[16];
    {
        const int lo5r = (lane & 7)
                       | (((((w >> 1) & 1) ^ ((lane >> 3) & 1))) << 3)
                       | (((((w >> 2) & 1) ^ ((lane >> 4) & 1))) << 4);
        const int hibase = ((lane >> 3) & 1) | (((lane >> 4) & 1) << 1) | ((w & 1) << 2);
        #pragma unroll
        for (int k2 = 0; k2 < 8; k2++) {
            float2 f = __half22float2(smB[((hibase | (k2 << 3)) << 5) | lo5r]);
            uu[2*k2]   = f.x;   // i0 = 0
            uu[2*k2+1] = f.y;   // i0 = 1
        }
    }

    // ---- stage 3 (fp32): butterfly k2 bits (i9,i10,i11) = uu-index bits 1..3 ----
    #pragma unroll
    for (int m = 2; m < 16; m <<= 1) {
        #pragma unroll
        for (int r = 0; r < 16; r++) {
            if ((r & m) == 0) {
                float a = uu[r], b = uu[r | m];
                uu[r]     = a + b;
                uu[r | m] = a - b;
            }
        }
    }

    // ---- scaled streaming store: o = (k2<<9)|(w<<6)|(lane<<1)|i0 -> 256B/warp contiguous ----
    const float scale = 0.015625f;   // 1/sqrt(4096)
    float* orow = out + (size_t)row * N;
    const int ob = (w << 6) | (lane << 1);
    #pragma unroll
    for (int k2 = 0; k2 < 8; k2++) {
        float2 f2 = make_float2(uu[2*k2] * scale, uu[2*k2+1] * scale);
        __stcs(reinterpret_cast<float2*>(orow + (ob | (k2 << 9))), f2);
    }
}

extern "C" void kernel_launch(void* const* d_in, const int* in_sizes, int n_in,
                              void* d_out, int out_size)
{
    const float* x = (const float*)d_in[0];
    const float* s = (const float*)d_in[1];
    float* out     = (float*)d_out;

    const int rows = in_sizes[0] / N;   // 16384
    fwht_kernel<<<rows, THREADS>>>(x, s, out);
}